// round 10
// baseline (speedup 1.0000x reference)
#include <cuda_runtime.h>
#include <cuda_bf16.h>
#include <cstdint>

#define N_NODE 100000
#define N_EDGE 800000
#define EMB 128
#define PITCH 40   // bf16 elems per smem row: 32 data + 8 pad = 80 bytes

// ---------------- static device scratch (allocation-free) ----------------
__device__ float g_h0[N_NODE * EMB];
__device__ float g_h1[N_NODE * EMB];
__device__ float g_n0[N_NODE * EMB];
__device__ float g_n1[N_NODE * EMB];
__device__ float g_E11[N_NODE * EMB];
__device__ float g_E01[N_NODE * EMB];
__device__ float g_E10[N_NODE * EMB];
__device__ float g_E00[N_NODE * EMB];
__device__ float g_a11[N_NODE * EMB];
__device__ float g_cat0[N_NODE * 256];   // [agg10 | agg00]
__device__ float g_cat1[N_NODE * 384];   // [T(256) | agg01(128)]
__device__ float g_esum[4 * N_NODE * 16];
__device__ float g_stats[1024];
// CSR per edge type
__device__ int g_cnt[4 * N_NODE];
__device__ int g_rp[4 * N_NODE];
__device__ int g_cur[4 * N_NODE];
__device__ int g_perm[4 * N_EDGE];
// pre-transposed / pre-split / pre-scaled weights: [N][K] bf16 hi/lo
__device__ __align__(16) __nv_bfloat16 g_bth[147456];
__device__ __align__(16) __nv_bfloat16 g_btl[147456];
__device__ float g_biasc[1024];

// ---------------- tiny utility kernels ----------------
__global__ void k_zero(float* __restrict__ p, int n4) {
    float4 z = make_float4(0.f, 0.f, 0.f, 0.f);
    for (int i = blockIdx.x * blockDim.x + threadIdx.x; i < n4;
         i += gridDim.x * blockDim.x)
        reinterpret_cast<float4*>(p)[i] = z;
}

__device__ __forceinline__ void red_add_v4(float* p, float4 v) {
    asm volatile("red.global.add.v4.f32 [%0], {%1,%2,%3,%4};"
                 :: "l"(p), "f"(v.x), "f"(v.y), "f"(v.z), "f"(v.w)
                 : "memory");
}

// ---------------- CSR build ----------------
__global__ void k_hist(const int* __restrict__ dst, int* __restrict__ cnt) {
    for (int i = blockIdx.x * blockDim.x + threadIdx.x; i < N_EDGE;
         i += gridDim.x * blockDim.x)
        atomicAdd(&cnt[__ldg(&dst[i])], 1);
}

// single-block exclusive scan over N_NODE ints -> rp, cur
__global__ __launch_bounds__(1024) void k_scan(const int* __restrict__ cnt,
                                               int* __restrict__ rp,
                                               int* __restrict__ cur) {
    __shared__ int sp[1024];
    const int t = threadIdx.x;
    const int per = (N_NODE + 1023) / 1024;
    const int base = t * per;
    int sum = 0;
    for (int i = 0; i < per; i++) {
        int idx = base + i;
        if (idx < N_NODE) sum += cnt[idx];
    }
    sp[t] = sum;
    __syncthreads();
    for (int off = 1; off < 1024; off <<= 1) {
        int v = (t >= off) ? sp[t - off] : 0;
        __syncthreads();
        sp[t] += v;
        __syncthreads();
    }
    int run = (t > 0) ? sp[t - 1] : 0;
    for (int i = 0; i < per; i++) {
        int idx = base + i;
        if (idx < N_NODE) {
            rp[idx] = run;
            cur[idx] = run;
            run += cnt[idx];
        }
    }
}

__global__ void k_fill(const int* __restrict__ src, const int* __restrict__ dst,
                       int* __restrict__ cur, int* __restrict__ perm) {
    for (int i = blockIdx.x * blockDim.x + threadIdx.x; i < N_EDGE;
         i += gridDim.x * blockDim.x) {
        int d = __ldg(&dst[i]);
        int pos = atomicAdd(&cur[d], 1);
        perm[pos] = __ldg(&src[i]);
    }
}

// ---------------- edge phase: scatter 16-wide ea sums ----------------
__global__ void k_edge_sum(const float* __restrict__ ea, const int* __restrict__ dst,
                           float* __restrict__ Esum) {
    const int n = N_EDGE * 4;
    for (int i = blockIdx.x * blockDim.x + threadIdx.x; i < n;
         i += gridDim.x * blockDim.x) {
        int e = i >> 2, q = i & 3;
        int d = __ldg(&dst[e]);
        float4 v = *reinterpret_cast<const float4*>(ea + (size_t)e * 16 + q * 4);
        red_add_v4(Esum + (size_t)d * 16 + q * 4, v);
    }
}

// E[r] = Esum[r] @ We + cnt[r]*be   (one warp per node row)
__global__ void k_edge_gemm(const float* __restrict__ Esum, const int* __restrict__ cnt,
                            const float* __restrict__ We, const float* __restrict__ be,
                            float* __restrict__ Eout) {
    __shared__ float sW[16 * EMB];
    for (int i = threadIdx.x; i < 16 * EMB; i += blockDim.x) sW[i] = We[i];
    __syncthreads();
    const int lane = threadIdx.x & 31;
    const int warp = (blockIdx.x * blockDim.x + threadIdx.x) >> 5;
    const int nwarp = (gridDim.x * blockDim.x) >> 5;
    const int c0 = lane * 4;
    const float4 bev = *reinterpret_cast<const float4*>(be + c0);
    for (int r = warp; r < N_NODE; r += nwarp) {
        float av = (lane < 16) ? Esum[(size_t)r * 16 + lane] : 0.f;
        float dg = (float)__ldg(&cnt[r]);
        float4 acc = make_float4(dg * bev.x, dg * bev.y, dg * bev.z, dg * bev.w);
#pragma unroll
        for (int k = 0; k < 16; k++) {
            float a = __shfl_sync(0xffffffffu, av, k);
            float4 w = *reinterpret_cast<const float4*>(sW + k * EMB + c0);
            acc.x += a * w.x; acc.y += a * w.y; acc.z += a * w.z; acc.w += a * w.w;
        }
        *reinterpret_cast<float4*>(Eout + (size_t)r * EMB + c0) = acc;
    }
}

// ---------------- CSR gather aggregation (1 warp per dst row) ----------------
// out[r*ldc+off .. +128] = E[r] (+ selfc*hself[r]) + sum_{e in CSR[r]} h[perm[e]]
__global__ __launch_bounds__(256) void k_gather(
    const int* __restrict__ rp, const int* __restrict__ cnt,
    const int* __restrict__ perm, const float* __restrict__ h,
    const float* __restrict__ E,
    const float* __restrict__ hself, float selfc,
    float* __restrict__ out, int ldc, int coloff) {
    const int lane = threadIdx.x & 31;
    const int warp = (blockIdx.x << 3) + (threadIdx.x >> 5);
    if (warp >= N_NODE) return;
    const int r = warp;
    const int c0 = lane * 4;
    const int start = __ldg(&rp[r]);
    const int num = __ldg(&cnt[r]);
    float4 acc = *reinterpret_cast<const float4*>(E + (size_t)r * EMB + c0);
    if (hself) {
        float4 hv = *reinterpret_cast<const float4*>(hself + (size_t)r * EMB + c0);
        acc.x += selfc * hv.x; acc.y += selfc * hv.y;
        acc.z += selfc * hv.z; acc.w += selfc * hv.w;
    }
    int e = start;
    const int end = start + num;
    for (; e + 1 < end; e += 2) {
        int s0 = __ldg(&perm[e]), s1 = __ldg(&perm[e + 1]);
        float4 v0 = *reinterpret_cast<const float4*>(h + (size_t)s0 * EMB + c0);
        float4 v1 = *reinterpret_cast<const float4*>(h + (size_t)s1 * EMB + c0);
        acc.x += v0.x + v1.x; acc.y += v0.y + v1.y;
        acc.z += v0.z + v1.z; acc.w += v0.w + v1.w;
    }
    if (e < end) {
        int s0 = __ldg(&perm[e]);
        float4 v0 = *reinterpret_cast<const float4*>(h + (size_t)s0 * EMB + c0);
        acc.x += v0.x; acc.y += v0.y; acc.z += v0.z; acc.w += v0.w;
    }
    *reinterpret_cast<float4*>(out + (size_t)r * ldc + coloff + c0) = acc;
}

// ---------------- weight prep: Bcat -> [N][K] bf16 hi/lo, scaled; combined bias ----------------
__global__ void k_prep(const float* __restrict__ B1, const float* __restrict__ B2,
                       int Kb, int K, int Ngm, int Nout, float s1, float s2,
                       const float* __restrict__ b1, const float* __restrict__ b2,
                       __nv_bfloat16* __restrict__ oh, __nv_bfloat16* __restrict__ ol,
                       float* __restrict__ ob) {
    const int tot = Nout * K;
    for (int i = blockIdx.x * blockDim.x + threadIdx.x; i < tot;
         i += gridDim.x * blockDim.x) {
        int n = i / K, k = i - n * K;
        float v = (k < Kb) ? s1 * B1[(size_t)k * Ngm + n]
                           : s2 * B2[(size_t)(k - Kb) * Ngm + n];
        __nv_bfloat16 h = __float2bfloat16(v);
        oh[i] = h;
        ol[i] = __float2bfloat16(v - __bfloat162float(h));
        if (k == 0) ob[n] = s1 * b1[n] + s2 * b2[n];
    }
}

// ---------------- warp-MMA split-bf16 GEMM (legacy HMMA path) ----------------
__device__ __forceinline__ uint32_t s2u(const void* p) {
    uint32_t a;
    asm("{ .reg .u64 t; cvta.to.shared.u64 t, %1; cvt.u32.u64 %0, t; }"
        : "=r"(a) : "l"(p));
    return a;
}
__device__ __forceinline__ void ldsm4(uint32_t* r, uint32_t addr) {
    asm volatile("ldmatrix.sync.aligned.m8n8.x4.shared.b16 {%0,%1,%2,%3}, [%4];"
                 : "=r"(r[0]), "=r"(r[1]), "=r"(r[2]), "=r"(r[3]) : "r"(addr));
}
__device__ __forceinline__ void ldsm2(uint32_t* r, uint32_t addr) {
    asm volatile("ldmatrix.sync.aligned.m8n8.x2.shared.b16 {%0,%1}, [%2];"
                 : "=r"(r[0]), "=r"(r[1]) : "r"(addr));
}
__device__ __forceinline__ void mma16816(float* c, const uint32_t* a, const uint32_t* b) {
    asm volatile(
        "mma.sync.aligned.m16n8k16.row.col.f32.bf16.bf16.f32 "
        "{%0,%1,%2,%3}, {%4,%5,%6,%7}, {%8,%9}, {%0,%1,%2,%3};"
        : "+f"(c[0]), "+f"(c[1]), "+f"(c[2]), "+f"(c[3])
        : "r"(a[0]), "r"(a[1]), "r"(a[2]), "r"(a[3]), "r"(b[0]), "r"(b[1]));
}
__device__ __forceinline__ uint32_t pk2(float a, float b) {
    __nv_bfloat162 h = __floats2bfloat162_rn(a, b);
    return *reinterpret_cast<uint32_t*>(&h);
}

__global__ __launch_bounds__(256, 2) void k_mma_gemm(
    const float* __restrict__ A, int lda, int M, int K,
    const __nv_bfloat16* __restrict__ Bh, const __nv_bfloat16* __restrict__ Bl,
    const float* __restrict__ biasc,
    float* __restrict__ C, int ldc, int relu) {
    __shared__ __nv_bfloat16 sAh[128 * PITCH], sAl[128 * PITCH];
    __shared__ __nv_bfloat16 sBh[128 * PITCH], sBl[128 * PITCH];
    const int t = threadIdx.x, lane = t & 31, wid = t >> 5;
    const int rowBase = blockIdx.y * 128;
    const int n0g = blockIdx.x * 128;
    const int wm = (wid >> 1) * 32, wn = (wid & 1) * 64;
    const uint32_t uAh = s2u(sAh), uAl = s2u(sAl);
    const uint32_t uBh = s2u(sBh), uBl = s2u(sBl);

    float acc[2][8][4];
#pragma unroll
    for (int i = 0; i < 2; i++)
#pragma unroll
        for (int j = 0; j < 8; j++)
#pragma unroll
            for (int q = 0; q < 4; q++) acc[i][j][q] = 0.f;

    const int li = lane & 7;
    const int a_row = (lane >> 3 & 1) * 8 + li;
    const int a_kof = (lane >> 4) * 8;
    const int b_row = li;
    const int b_kof = ((lane >> 3) & 1) * 8;
    const int arow = t >> 1, acol = (t & 1) * 16;

    for (int k0 = 0; k0 < K; k0 += 32) {
        {
            const int gr = rowBase + arow;
            float f[16];
            if (gr < M) {
                const float* ap = A + (size_t)gr * lda + k0 + acol;
#pragma unroll
                for (int q = 0; q < 4; q++) {
                    float4 v = __ldg(reinterpret_cast<const float4*>(ap + q * 4));
                    f[4 * q] = v.x; f[4 * q + 1] = v.y;
                    f[4 * q + 2] = v.z; f[4 * q + 3] = v.w;
                }
            } else {
#pragma unroll
                for (int q = 0; q < 16; q++) f[q] = 0.f;
            }
            uint32_t h[8], l[8];
#pragma unroll
            for (int q = 0; q < 8; q++) {
                float x0 = f[2 * q], x1 = f[2 * q + 1];
                float r0 = x0 - __bfloat162float(__float2bfloat16(x0));
                float r1 = x1 - __bfloat162float(__float2bfloat16(x1));
                h[q] = pk2(x0, x1);
                l[q] = pk2(r0, r1);
            }
            __nv_bfloat16* dh = sAh + arow * PITCH + acol;
            __nv_bfloat16* dl = sAl + arow * PITCH + acol;
            reinterpret_cast<uint4*>(dh)[0] = make_uint4(h[0], h[1], h[2], h[3]);
            reinterpret_cast<uint4*>(dh)[1] = make_uint4(h[4], h[5], h[6], h[7]);
            reinterpret_cast<uint4*>(dl)[0] = make_uint4(l[0], l[1], l[2], l[3]);
            reinterpret_cast<uint4*>(dl)[1] = make_uint4(l[4], l[5], l[6], l[7]);
        }
        {
            const int brow = t >> 1, bcol = (t & 1) * 16;
            const size_t go = (size_t)(n0g + brow) * K + k0 + bcol;
            const uint4* bhp = reinterpret_cast<const uint4*>(Bh + go);
            const uint4* blp = reinterpret_cast<const uint4*>(Bl + go);
            __nv_bfloat16* dh = sBh + brow * PITCH + bcol;
            __nv_bfloat16* dl = sBl + brow * PITCH + bcol;
            reinterpret_cast<uint4*>(dh)[0] = __ldg(bhp);
            reinterpret_cast<uint4*>(dh)[1] = __ldg(bhp + 1);
            reinterpret_cast<uint4*>(dl)[0] = __ldg(blp);
            reinterpret_cast<uint4*>(dl)[1] = __ldg(blp + 1);
        }
        __syncthreads();

#pragma unroll
        for (int ks = 0; ks < 32; ks += 16) {
            uint32_t ah[2][4], al[2][4];
#pragma unroll
            for (int mt = 0; mt < 2; mt++) {
                uint32_t off = ((wm + mt * 16 + a_row) * PITCH + ks + a_kof) * 2;
                ldsm4(ah[mt], uAh + off);
                ldsm4(al[mt], uAl + off);
            }
#pragma unroll
            for (int nt = 0; nt < 8; nt++) {
                uint32_t bh[2], bl[2];
                uint32_t off = ((wn + nt * 8 + b_row) * PITCH + ks + b_kof) * 2;
                ldsm2(bh, uBh + off);
                ldsm2(bl, uBl + off);
#pragma unroll
                for (int mt = 0; mt < 2; mt++) {
                    mma16816(acc[mt][nt], ah[mt], bh);
                    mma16816(acc[mt][nt], ah[mt], bl);
                    mma16816(acc[mt][nt], al[mt], bh);
                }
            }
        }
        __syncthreads();
    }

    const int r4 = lane >> 2, c2 = (lane & 3) * 2;
#pragma unroll
    for (int mt = 0; mt < 2; mt++) {
        const int row0 = rowBase + wm + mt * 16 + r4;
        const int row1 = row0 + 8;
#pragma unroll
        for (int nt = 0; nt < 8; nt++) {
            const int col = n0g + wn + nt * 8 + c2;
            float b0 = __ldg(biasc + col), b1 = __ldg(biasc + col + 1);
            float v0 = acc[mt][nt][0] + b0, v1 = acc[mt][nt][1] + b1;
            float v2 = acc[mt][nt][2] + b0, v3 = acc[mt][nt][3] + b1;
            if (relu) {
                v0 = fmaxf(v0, 0.f); v1 = fmaxf(v1, 0.f);
                v2 = fmaxf(v2, 0.f); v3 = fmaxf(v3, 0.f);
            }
            if (row0 < M)
                *reinterpret_cast<float2*>(C + (size_t)row0 * ldc + col) =
                    make_float2(v0, v1);
            if (row1 < M)
                *reinterpret_cast<float2*>(C + (size_t)row1 * ldc + col) =
                    make_float2(v2, v3);
        }
    }
}

// ---------------- BatchNorm ----------------
__global__ void k_bn_stats(const float* __restrict__ X, int M, float* __restrict__ stats) {
    const int col = threadIdx.x & 127;
    const int rp = threadIdx.x >> 7;
    float s = 0.f, q = 0.f;
    for (int r = blockIdx.x * 2 + rp; r < M; r += gridDim.x * 2) {
        float v = X[(size_t)r * EMB + col];
        s += v; q += v * v;
    }
    atomicAdd(&stats[col], s);
    atomicAdd(&stats[EMB + col], q);
}

__global__ void k_bn_finalize(float* __restrict__ stats, const float* __restrict__ gamma,
                              const float* __restrict__ beta, int layer, float invM) {
    int c = threadIdx.x;
    int type = c >> 7, col = c & 127;
    float mu = stats[type * 256 + col] * invM;
    float var = stats[type * 256 + 128 + col] * invM - mu * mu;
    float a = gamma[layer * EMB + col] * rsqrtf(var + 1e-5f);
    float b = beta[layer * EMB + col] - a * mu;
    stats[512 + type * 256 + col] = a;
    stats[512 + type * 256 + 128 + col] = b;
}

__global__ void k_bn_apply2(const float* __restrict__ X0, float* __restrict__ Y0,
                            const float* __restrict__ X1, float* __restrict__ Y1,
                            const float* __restrict__ stats, int relu) {
    const int n = N_NODE * EMB;
    for (int i = blockIdx.x * blockDim.x + threadIdx.x; i < 2 * n;
         i += gridDim.x * blockDim.x) {
        int col = i & 127;
        if (i < n) {
            float v = stats[512 + col] * X0[i] + stats[512 + 128 + col];
            if (relu) v = fmaxf(v, 0.f);
            Y0[i] = v;
        } else {
            int j = i - n;
            float v = stats[768 + col] * X1[j] + stats[768 + 128 + col];
            if (relu) v = fmaxf(v, 0.f);
            Y1[j] = v;
        }
    }
}

// ---------------- host orchestration ----------------
extern "C" void kernel_launch(void* const* d_in, const int* in_sizes, int n_in,
                              void* d_out, int out_size) {
    (void)in_sizes; (void)n_in; (void)out_size;
    const float* x0   = (const float*)d_in[0];
    const float* x1   = (const float*)d_in[1];
    const float* ea11 = (const float*)d_in[2];
    const float* ea10 = (const float*)d_in[3];
    const float* ea01 = (const float*)d_in[4];
    const float* ea00 = (const float*)d_in[5];
    const int*   ei11 = (const int*)d_in[6];
    const int*   ei10 = (const int*)d_in[7];
    const int*   ei01 = (const int*)d_in[8];
    const int*   ei00 = (const int*)d_in[9];
    const float* Wx  = (const float*)d_in[10];
    const float* bx  = (const float*)d_in[11];
    const float* We  = (const float*)d_in[12];
    const float* be  = (const float*)d_in[13];
    const float* gW1 = (const float*)d_in[14];
    const float* gb1 = (const float*)d_in[15];
    const float* gW2 = (const float*)d_in[16];
    const float* gb2 = (const float*)d_in[17];
    const float* W10 = (const float*)d_in[18];
    const float* b10 = (const float*)d_in[19];
    const float* W01 = (const float*)d_in[20];
    const float* b01 = (const float*)d_in[21];
    const float* W00 = (const float*)d_in[22];
    const float* b00 = (const float*)d_in[23];
    const float* gamma = (const float*)d_in[24];
    const float* beta  = (const float*)d_in[25];
    float* out = (float*)d_out;

    float *h0, *h1, *n0b, *n1b, *E11, *E01, *E10, *E00, *a11, *cat0, *cat1;
    float *esum, *stats, *biasc;
    int *cnt, *rp, *cur, *perm;
    __nv_bfloat16 *bth, *btl;
    cudaGetSymbolAddress((void**)&h0,   g_h0);
    cudaGetSymbolAddress((void**)&h1,   g_h1);
    cudaGetSymbolAddress((void**)&n0b,  g_n0);
    cudaGetSymbolAddress((void**)&n1b,  g_n1);
    cudaGetSymbolAddress((void**)&E11,  g_E11);
    cudaGetSymbolAddress((void**)&E01,  g_E01);
    cudaGetSymbolAddress((void**)&E10,  g_E10);
    cudaGetSymbolAddress((void**)&E00,  g_E00);
    cudaGetSymbolAddress((void**)&a11,  g_a11);
    cudaGetSymbolAddress((void**)&cat0, g_cat0);
    cudaGetSymbolAddress((void**)&cat1, g_cat1);
    cudaGetSymbolAddress((void**)&esum, g_esum);
    cudaGetSymbolAddress((void**)&stats, g_stats);
    cudaGetSymbolAddress((void**)&cnt,  g_cnt);
    cudaGetSymbolAddress((void**)&rp,   g_rp);
    cudaGetSymbolAddress((void**)&cur,  g_cur);
    cudaGetSymbolAddress((void**)&perm, g_perm);
    cudaGetSymbolAddress((void**)&bth,  g_bth);
    cudaGetSymbolAddress((void**)&btl,  g_btl);
    cudaGetSymbolAddress((void**)&biasc, g_biasc);

    // ---- weight prep ----
    k_prep<<<128, 256>>>(Wx, Wx, 256, 256, 128, 128, 1.f, 0.f, bx, bx,
                         bth, btl, biasc);
    k_prep<<<128, 256>>>(gW1, gW1, 128, 128, 256, 256, 1.f, 0.f, gb1, gb1,
                         bth + 32768, btl + 32768, biasc + 256);
    k_prep<<<192, 256>>>(gW2, W01, 256, 384, 128, 128, 0.5f, 0.05f, gb2, b01,
                         bth + 65536, btl + 65536, biasc + 512);
    k_prep<<<128, 256>>>(W10, W00, 128, 256, 128, 128, 0.05f, 0.05f, b10, b00,
                         bth + 114688, btl + 114688, biasc + 768);

    // ---- CSR build: hist -> scan -> fill (per edge type) ----
    k_zero<<<256, 256>>>((float*)cnt, N_NODE);   // 4*N ints = N float4s
    k_hist<<<1600, 256>>>(ei11 + N_EDGE, cnt + 0 * N_NODE);
    k_hist<<<1600, 256>>>(ei01 + N_EDGE, cnt + 1 * N_NODE);
    k_hist<<<1600, 256>>>(ei10 + N_EDGE, cnt + 2 * N_NODE);
    k_hist<<<1600, 256>>>(ei00 + N_EDGE, cnt + 3 * N_NODE);
    for (int ty = 0; ty < 4; ty++)
        k_scan<<<1, 1024>>>(cnt + ty * N_NODE, rp + ty * N_NODE, cur + ty * N_NODE);
    k_fill<<<1600, 256>>>(ei11, ei11 + N_EDGE, cur + 0 * N_NODE, perm + 0 * N_EDGE);
    k_fill<<<1600, 256>>>(ei01, ei01 + N_EDGE, cur + 1 * N_NODE, perm + 1 * N_EDGE);
    k_fill<<<1600, 256>>>(ei10, ei10 + N_EDGE, cur + 2 * N_NODE, perm + 2 * N_EDGE);
    k_fill<<<1600, 256>>>(ei00, ei00 + N_EDGE, cur + 3 * N_NODE, perm + 3 * N_EDGE);

    // ---- edge-attr phase: 16-wide sums + per-node GEMV ----
    k_zero<<<2048, 256>>>(esum, 4 * N_NODE * 4);
    k_edge_sum<<<1600, 256>>>(ea11, ei11 + N_EDGE, esum + 0 * N_NODE * 16);
    k_edge_sum<<<1600, 256>>>(ea01, ei01 + N_EDGE, esum + 1 * N_NODE * 16);
    k_edge_sum<<<1600, 256>>>(ea10, ei10 + N_EDGE, esum + 2 * N_NODE * 16);
    k_edge_sum<<<1600, 256>>>(ea00, ei00 + N_EDGE, esum + 3 * N_NODE * 16);
    k_edge_gemm<<<1024, 256>>>(esum + 0 * N_NODE * 16, cnt + 0 * N_NODE, We, be, E11);
    k_edge_gemm<<<1024, 256>>>(esum + 1 * N_NODE * 16, cnt + 1 * N_NODE, We, be, E01);
    k_edge_gemm<<<1024, 256>>>(esum + 2 * N_NODE * 16, cnt + 2 * N_NODE, We, be, E10);
    k_edge_gemm<<<1024, 256>>>(esum + 3 * N_NODE * 16, cnt + 3 * N_NODE, We, be, E00);

    const int MT = (N_NODE + 127) / 128;   // 782 row tiles
    dim3 gg1(1, MT), gg2(2, MT);

    // Input embeddings: h = x @ Wx + bx
    k_mma_gemm<<<gg1, 256>>>(x0, 256, N_NODE, 256, bth, btl, biasc, h0, 128, 0);
    k_mma_gemm<<<gg1, 256>>>(x1, 256, N_NODE, 256, bth, btl, biasc, h1, 128, 0);

    const int GGRID = (N_NODE + 7) / 8;    // 1 warp per dst row, 8 warps/block
    float* cur0 = h0;
    float* cur1 = h1;

    for (int layer = 0; layer < 2; layer++) {
        float* o0 = (layer == 0) ? n0b : h0;
        float* o1 = (layer == 0) ? n1b : h1;

        // CSR gather aggregation (init + GIN self-term fused)
        k_gather<<<GGRID, 256>>>(rp + 0 * N_NODE, cnt + 0 * N_NODE, perm + 0 * N_EDGE,
                                 cur1, E11, cur1, 1.1f, a11, 128, 0);
        k_gather<<<GGRID, 256>>>(rp + 1 * N_NODE, cnt + 1 * N_NODE, perm + 1 * N_EDGE,
                                 cur0, E01, nullptr, 0.f, cat1, 384, 256);
        k_gather<<<GGRID, 256>>>(rp + 2 * N_NODE, cnt + 2 * N_NODE, perm + 2 * N_EDGE,
                                 cur1, E10, nullptr, 0.f, cat0, 256, 0);
        k_gather<<<GGRID, 256>>>(rp + 3 * N_NODE, cnt + 3 * N_NODE, perm + 3 * N_EDGE,
                                 cur0, E00, nullptr, 0.f, cat0, 256, 128);

        // T = relu(a11 @ gW1 + gb1) -> cat1 cols [0,256)
        k_mma_gemm<<<gg2, 256>>>(a11, 128, N_NODE, 128,
                                 bth + 32768, btl + 32768, biasc + 256,
                                 cat1, 384, 1);
        // new1 = [T | a01] @ [0.5*gW2 ; 0.05*W01] + combined bias
        k_mma_gemm<<<gg1, 256>>>(cat1, 384, N_NODE, 384,
                                 bth + 65536, btl + 65536, biasc + 512,
                                 o1, 128, 0);
        // new0 = [a10 | a00] @ [0.05*W10 ; 0.05*W00] + combined bias
        k_mma_gemm<<<gg1, 256>>>(cat0, 256, N_NODE, 256,
                                 bth + 114688, btl + 114688, biasc + 768,
                                 o0, 128, 0);

        // BatchNorm
        k_zero<<<1, 128>>>(stats, 128);
        k_bn_stats<<<1024, 256>>>(o0, N_NODE, stats);
        k_bn_stats<<<1024, 256>>>(o1, N_NODE, stats + 256);
        k_bn_finalize<<<1, 256>>>(stats, gamma, beta, layer, 1.f / N_NODE);
        int relu = (layer == 0) ? 1 : 0;
        float* dst0 = (layer == 0) ? o0 : out;
        float* dst1 = (layer == 0) ? o1 : out + (size_t)N_NODE * EMB;
        k_bn_apply2<<<2048, 256>>>(o0, dst0, o1, dst1, stats, relu);

        cur0 = o0;
        cur1 = o1;
    }
}